// round 10
// baseline (speedup 1.0000x reference)
#include <cuda_runtime.h>
#include <cuda_fp16.h>
#include <stdint.h>

#define B_    64
#define H_    6
#define N_    512
#define D_    32
#define NIDX  43
#define BH_   384
#define LOG2E 1.4426950408889634f

// attn smem: K image 32KB | V image 32 rows x 68 u4 | MLP weights | bias
#define SK_OFF   0
#define SV_OFF   32768
#define VROW_U   68
#define WT_OFF   (SV_OFF + D_*VROW_U*16)   // 67584, 512 floats
#define SB_OFF   (WT_OFF + 2048)           // 69632
#define SMEM_SZ  (SB_OFF + 192)            // 69824 -> 2 CTAs/SM
#define PREP_SMEM (128*33*4)               // 16896

// gmem image V: [bh][d(32)][w(64)] u4; w = kp*4+le, kp in [0,16), k0 = 32*kp+2*le:
//    {v(k0),v(k0+1)},{v(k0+8),v(k0+9)},{v(k0+16),v(k0+17)},{v(k0+24),v(k0+25)}
__device__ uint4 g_V[BH_ * D_ * 64];

// ---------------- helpers ----------------
__device__ __forceinline__ uint32_t pkf16(float x0, float x1) {
    uint32_t r; asm("cvt.rn.f16x2.f32 %0, %1, %2;" : "=r"(r) : "f"(x1), "f"(x0)); return r;
}
__device__ __forceinline__ float ex2f(float x) {
    float y; asm("ex2.approx.f32 %0, %1;" : "=f"(y) : "f"(x)); return y;
}
__device__ __forceinline__ void mma_f16(float c[4], const uint32_t a[4], uint32_t b0, uint32_t b1) {
    asm volatile(
        "mma.sync.aligned.m16n8k16.row.col.f32.f16.f16.f32 "
        "{%0,%1,%2,%3}, {%4,%5,%6,%7}, {%8,%9}, {%0,%1,%2,%3};\n"
        : "+f"(c[0]), "+f"(c[1]), "+f"(c[2]), "+f"(c[3])
        : "r"(a[0]), "r"(a[1]), "r"(a[2]), "r"(a[3]), "r"(b0), "r"(b1));
}
__device__ __forceinline__ void cp16(uint32_t dst, const void* src) {
    asm volatile("cp.async.cg.shared.global [%0], [%1], 16;" :: "r"(dst), "l"(src));
}
#define CP_COMMIT() asm volatile("cp.async.commit_group;" ::: "memory")
#define CP_WAIT0()  asm volatile("cp.async.wait_group 0;" ::: "memory")

__device__ __forceinline__ void ln_relu12(const float* x, const float* g, const float* b, float* y) {
    float mu = 0.f;
    #pragma unroll
    for (int j = 0; j < 12; j++) mu += x[j];
    mu *= (1.f / 12.f);
    float var = 0.f;
    #pragma unroll
    for (int j = 0; j < 12; j++) { float d = x[j] - mu; var += d * d; }
    var *= (1.f / 12.f);
    float inv = rsqrtf(var + 1e-5f);
    #pragma unroll
    for (int j = 0; j < 12; j++) {
        float t = (x[j] - mu) * inv * g[j] + b[j];
        y[j] = t > 0.f ? t : 0.f;
    }
}

// ---------------------------------------------------------------------------
// Kernel 0: prep — V image only; one block per (bh, 128-kv chunk)
// ---------------------------------------------------------------------------
__global__ __launch_bounds__(256) void prep_kernel(const float* __restrict__ v)
{
    extern __shared__ float sh[];
    const int t = threadIdx.x;
    const int bi = blockIdx.x;
    const int bh = bi >> 2, c = bi & 3;      // kv rows 128c..128c+127
    const float* vb = v + (size_t)bh * N_ * D_ + (size_t)(128 * c) * D_;

    for (int i = t; i < 128 * D_; i += 256) {
        int kv = i >> 5, d = i & 31;
        sh[kv * 33 + d] = vb[i];
    }
    __syncthreads();
    for (int i = t; i < D_ * 16; i += 256) {       // 512 u4 per chunk
        int d = i >> 4, wl = i & 15;               // wl = kpl*4 + le
        int kpl = wl >> 2, le = wl & 3;
        int k0 = 32 * kpl + 2 * le;
        uint4 w;
        w.x = pkf16(sh[(k0 +  0) * 33 + d], sh[(k0 +  1) * 33 + d]);
        w.y = pkf16(sh[(k0 +  8) * 33 + d], sh[(k0 +  9) * 33 + d]);
        w.z = pkf16(sh[(k0 + 16) * 33 + d], sh[(k0 + 17) * 33 + d]);
        w.w = pkf16(sh[(k0 + 24) * 33 + d], sh[(k0 + 25) * 33 + d]);
        g_V[(size_t)bh * (D_ * 64) + d * 64 + 16 * c + wl] = w;   // global w = 16c + wl
    }
}

// ---------------------------------------------------------------------------
// Kernel 1: flash attention — K convert + MLP fused in; V image via cp.async
// ---------------------------------------------------------------------------
__global__ __launch_bounds__(256, 2) void attn_kernel(
    const float* __restrict__ q, const float* __restrict__ k, float* __restrict__ out,
    const float* __restrict__ pw,  const float* __restrict__ pb,
    const float* __restrict__ g1,  const float* __restrict__ b1,
    const float* __restrict__ w1,  const float* __restrict__ bb1,
    const float* __restrict__ g2,  const float* __restrict__ b2,
    const float* __restrict__ w2,  const float* __restrict__ bb2,
    const float* __restrict__ g3,  const float* __restrict__ b3,
    const float* __restrict__ w3,  const float* __restrict__ bb3)
{
    extern __shared__ unsigned char smem[];
    uint32_t sb;
    asm("{ .reg .u64 t; cvta.to.shared.u64 t, %1; cvt.u32.u64 %0, t; }" : "=r"(sb) : "l"(smem));
    float* wts    = (float*)(smem + WT_OFF);
    float* biasSm = (float*)(smem + SB_OFF);

    const int qt = blockIdx.x, head = blockIdx.y, batch = blockIdx.z;
    const int bh = batch * H_ + head;
    const size_t bhOff = (size_t)bh * N_ * D_;
    const float* qb = q + bhOff;
    const float* kb = k + bhOff;
    const int tid = threadIdx.x;

    // V image fill (cp.async, no dependencies)
    {
        const uint4* gv = g_V + (size_t)bh * (D_ * 64);
        for (int i = tid; i < D_ * 64; i += 256) {
            int d = i >> 6, w_ = i & 63;
            cp16(sb + SV_OFF + (d * VROW_U + w_) * 16, gv + i);
        }
        CP_COMMIT();
    }

    // MLP weights -> smem
    if (tid < 36)  wts[tid] = pw[tid];
    if (tid < 12) {
        wts[36+tid]=pb[tid];  wts[48+tid]=g1[tid]; wts[60+tid]=b1[tid]; wts[216+tid]=bb1[tid];
        wts[228+tid]=g2[tid]; wts[240+tid]=b2[tid]; wts[396+tid]=bb2[tid];
        wts[408+tid]=g3[tid]; wts[420+tid]=b3[tid];
    }
    if (tid < 144) { wts[72+tid]=w1[tid]; wts[252+tid]=w2[tid]; }
    if (tid >= 144 && tid < 216) wts[432+tid-144] = w3[tid-144];
    if (tid >= 216 && tid < 222) wts[504+tid-216] = bb3[tid-216];

    // K convert: raw fp32 -> fp16 image in smem (coalesced)
    {
        uint4* Kimg = (uint4*)(smem + SK_OFF);
        for (int i = tid; i < N_ * 4; i += 256) {
            int n = i >> 2, le = i & 3, c0 = le * 2;
            const float* row = kb + (size_t)n * D_;
            float2 f0 = *(const float2*)(row + c0);
            float2 f1 = *(const float2*)(row + c0 + 8);
            float2 f2 = *(const float2*)(row + c0 + 16);
            float2 f3 = *(const float2*)(row + c0 + 24);
            uint4 w;
            w.x = pkf16(f0.x, f0.y); w.y = pkf16(f1.x, f1.y);
            w.z = pkf16(f2.x, f2.y); w.w = pkf16(f3.x, f3.y);
            Kimg[i] = w;
        }
    }

    const int warp = tid >> 5, lane = tid & 31;
    const int lq = lane >> 2, le = lane & 3, e0 = le * 2;
    const int r0 = qt * 128 + warp * 16 + lq;
    const int r1 = r0 + 8;
    const int sq0 = (r0 >> 6) + ((r0 >> 3) & 7) + (r0 & 7);

    // Q fragments (single fp16, scale folded into log2 domain)
    const float scale = 0.17677669529663687f * LOG2E;
    uint32_t aq[2][4];
    #pragma unroll
    for (int ks = 0; ks < 2; ks++) {
        int cb = ks * 16 + e0;
        aq[ks][0] = pkf16(qb[(size_t)r0 * D_ + cb] * scale,     qb[(size_t)r0 * D_ + cb + 1] * scale);
        aq[ks][1] = pkf16(qb[(size_t)r1 * D_ + cb] * scale,     qb[(size_t)r1 * D_ + cb + 1] * scale);
        aq[ks][2] = pkf16(qb[(size_t)r0 * D_ + cb + 8] * scale, qb[(size_t)r0 * D_ + cb + 9] * scale);
        aq[ks][3] = pkf16(qb[(size_t)r1 * D_ + cb + 8] * scale, qb[(size_t)r1 * D_ + cb + 9] * scale);
    }

    __syncthreads();   // wts + K image visible

    // in-CTA MLP: this head's 43 bias values (overlaps V cp.async in flight)
    if (tid < NIDX) {
        float c0 = -7.0f, c1 = (float)(tid / 15) - 7.0f, c2 = (float)(tid % 15) - 7.0f;
        float x[12], y[12];
        #pragma unroll
        for (int j = 0; j < 12; j++)
            x[j] = c0 * wts[j] + c1 * wts[12 + j] + c2 * wts[24 + j] + wts[36 + j];
        ln_relu12(x, wts+48, wts+60, y);
        #pragma unroll
        for (int j = 0; j < 12; j++) {
            float s = wts[216 + j];
            #pragma unroll
            for (int i = 0; i < 12; i++) s += y[i] * wts[72 + i * 12 + j];
            x[j] = s;
        }
        ln_relu12(x, wts+228, wts+240, y);
        #pragma unroll
        for (int j = 0; j < 12; j++) {
            float s = wts[396 + j];
            #pragma unroll
            for (int i = 0; i < 12; i++) s += y[i] * wts[252 + i * 12 + j];
            x[j] = s;
        }
        ln_relu12(x, wts+408, wts+420, y);
        float s = wts[504 + head];
        #pragma unroll
        for (int i = 0; i < 12; i++) s += y[i] * wts[432 + i * H_ + head];
        biasSm[tid] = s * LOG2E;
    }

    CP_WAIT0();
    __syncthreads();   // V image + biasSm visible

    const int A1 = sq0 + 22 - e0;          // in [16,42]
    float br[17];
    #pragma unroll
    for (int u = 0; u < 17; u++) br[u] = biasSm[A1 - u];

    const uint4* Ks = (const uint4*)(smem + SK_OFF);
    const uint4* Vs = (const uint4*)(smem + SV_OFF);

    float O[4][4];
    #pragma unroll
    for (int d = 0; d < 4; d++)
        #pragma unroll
        for (int j = 0; j < 4; j++) O[d][j] = 0.f;
    float l0 = 0.f, l1 = 0.f;

    #pragma unroll
    for (int ch64 = 0; ch64 < 8; ch64++) {
        float S[8][4];
        #pragma unroll
        for (int nt = 0; nt < 8; nt++) {
            S[nt][0] = br[ch64 + nt + 1];
            S[nt][1] = br[ch64 + nt + 2];
            S[nt][2] = br[ch64 + nt];
            S[nt][3] = br[ch64 + nt + 1];
        }
        #pragma unroll
        for (int nt = 0; nt < 8; nt++) {
            uint4 w = Ks[(ch64 * 64 + nt * 8 + lq) * 4 + le];
            mma_f16(S[nt], aq[0], w.x, w.y);
            mma_f16(S[nt], aq[1], w.z, w.w);
        }
        float ps0 = 0.f, ps1 = 0.f;
        #pragma unroll
        for (int nt = 0; nt < 8; nt++) {
            S[nt][0] = ex2f(S[nt][0]); S[nt][1] = ex2f(S[nt][1]);
            S[nt][2] = ex2f(S[nt][2]); S[nt][3] = ex2f(S[nt][3]);
            ps0 += S[nt][0] + S[nt][1];
            ps1 += S[nt][2] + S[nt][3];
        }
        l0 += ps0; l1 += ps1;
        #pragma unroll
        for (int kp2 = 0; kp2 < 2; kp2++) {
            const int j0 = kp2 * 2, j1 = j0 + 1;
            uint32_t ap0[4], ap1[4];
            ap0[0] = pkf16(S[2*j0][0],   S[2*j0][1]);
            ap0[1] = pkf16(S[2*j0][2],   S[2*j0][3]);
            ap0[2] = pkf16(S[2*j0+1][0], S[2*j0+1][1]);
            ap0[3] = pkf16(S[2*j0+1][2], S[2*j0+1][3]);
            ap1[0] = pkf16(S[2*j1][0],   S[2*j1][1]);
            ap1[1] = pkf16(S[2*j1][2],   S[2*j1][3]);
            ap1[2] = pkf16(S[2*j1+1][0], S[2*j1+1][1]);
            ap1[3] = pkf16(S[2*j1+1][2], S[2*j1+1][3]);
            const int wb = (ch64 * 2 + kp2) * 4 + le;
            #pragma unroll
            for (int dt = 0; dt < 4; dt++) {
                uint4 w = Vs[(dt * 8 + lq) * VROW_U + wb];
                mma_f16(O[dt], ap0, w.x, w.y);
                mma_f16(O[dt], ap1, w.z, w.w);
            }
        }
    }

    // finalize
    l0 += __shfl_xor_sync(0xffffffffu, l0, 1);
    l0 += __shfl_xor_sync(0xffffffffu, l0, 2);
    l1 += __shfl_xor_sync(0xffffffffu, l1, 1);
    l1 += __shfl_xor_sync(0xffffffffu, l1, 2);
    float i0 = 1.f / l0, i1 = 1.f / l1;
    float* ob = out + bhOff;
    #pragma unroll
    for (int dt = 0; dt < 4; dt++) {
        int c = dt * 8 + e0;
        float2 o01; o01.x = O[dt][0] * i0; o01.y = O[dt][1] * i0;
        float2 o23; o23.x = O[dt][2] * i1; o23.y = O[dt][3] * i1;
        *(float2*)(ob + (size_t)r0 * D_ + c) = o01;
        *(float2*)(ob + (size_t)r1 * D_ + c) = o23;
    }
}

// ---------------------------------------------------------------------------
extern "C" void kernel_launch(void* const* d_in, const int* in_sizes, int n_in,
                              void* d_out, int out_size)
{
    const float* q = (const float*)d_in[0];
    const float* k = (const float*)d_in[1];
    const float* v = (const float*)d_in[2];
    int base = (in_sizes[3] == 36) ? 3 : 6;
    const float* pw  = (const float*)d_in[base + 0];
    const float* pb  = (const float*)d_in[base + 1];
    const float* g1  = (const float*)d_in[base + 2];
    const float* b1  = (const float*)d_in[base + 3];
    const float* w1  = (const float*)d_in[base + 4];
    const float* bb1 = (const float*)d_in[base + 5];
    const float* g2  = (const float*)d_in[base + 6];
    const float* b2  = (const float*)d_in[base + 7];
    const float* w2  = (const float*)d_in[base + 8];
    const float* bb2 = (const float*)d_in[base + 9];
    const float* g3  = (const float*)d_in[base + 10];
    const float* b3  = (const float*)d_in[base + 11];
    const float* w3  = (const float*)d_in[base + 12];
    const float* bb3 = (const float*)d_in[base + 13];
    float* out = (float*)d_out;

    cudaFuncSetAttribute(prep_kernel, cudaFuncAttributeMaxDynamicSharedMemorySize, PREP_SMEM);
    cudaFuncSetAttribute(attn_kernel, cudaFuncAttributeMaxDynamicSharedMemorySize, SMEM_SZ);

    prep_kernel<<<BH_ * 4, 256, PREP_SMEM>>>(v);

    dim3 grid(N_ / 128, H_, B_);
    attn_kernel<<<grid, 256, SMEM_SZ>>>(q, k, out, pw, pb, g1, b1, w1, bb1,
                                        g2, b2, w2, bb2, g3, b3, w3, bb3);
}

// round 11
// speedup vs baseline: 1.3163x; 1.3163x over previous
#include <cuda_runtime.h>
#include <cuda_fp16.h>
#include <stdint.h>

#define B_    64
#define H_    6
#define N_    512
#define D_    32
#define NIDX  43
#define BH_   384
#define LOG2E 1.4426950408889634f

// attn smem: K image 32KB | V image 32 rows x 68 u4 (64 used + 4 pad) | bias
#define SK_OFF   0
#define SV_OFF   32768
#define VROW_U   68
#define SB_OFF   (SV_OFF + D_*VROW_U*16)   // 67584
#define SMEM_SZ  (SB_OFF + 192)            // 67776 -> 2 CTAs/SM
#define PREP_SMEM (128*33*4)               // 16896

// gmem image V: [bh][d(32)][w(64)] u4; w = kp*4+le, kp in [0,16), k0 = 32*kp+2*le:
//    {v(k0),v(k0+1)},{v(k0+8),v(k0+9)},{v(k0+16),v(k0+17)},{v(k0+24),v(k0+25)}
__device__ uint4 g_K[BH_ * N_ * 4];
__device__ uint4 g_V[BH_ * D_ * 64];
__device__ float g_pos[H_ * NIDX];

// ---------------- helpers ----------------
__device__ __forceinline__ uint32_t pkf16(float x0, float x1) {
    uint32_t r; asm("cvt.rn.f16x2.f32 %0, %1, %2;" : "=r"(r) : "f"(x1), "f"(x0)); return r;
}
__device__ __forceinline__ uint32_t hadd2(uint32_t a, uint32_t b) {
    uint32_t r; asm("add.rn.f16x2 %0, %1, %2;" : "=r"(r) : "r"(a), "r"(b)); return r;
}
__device__ __forceinline__ uint32_t hex2(uint32_t a) {
    uint32_t r; asm("ex2.approx.f16x2 %0, %1;" : "=r"(r) : "r"(a)); return r;
}
__device__ __forceinline__ void mma_f16(float c[4], const uint32_t a[4], uint32_t b0, uint32_t b1) {
    asm volatile(
        "mma.sync.aligned.m16n8k16.row.col.f32.f16.f16.f32 "
        "{%0,%1,%2,%3}, {%4,%5,%6,%7}, {%8,%9}, {%0,%1,%2,%3};\n"
        : "+f"(c[0]), "+f"(c[1]), "+f"(c[2]), "+f"(c[3])
        : "r"(a[0]), "r"(a[1]), "r"(a[2]), "r"(a[3]), "r"(b0), "r"(b1));
}
// fresh accumulator (C = 0)
__device__ __forceinline__ void mma_f16_zc(float d[4], const uint32_t a[4], uint32_t b0, uint32_t b1) {
    asm volatile(
        "mma.sync.aligned.m16n8k16.row.col.f32.f16.f16.f32 "
        "{%0,%1,%2,%3}, {%4,%5,%6,%7}, {%8,%9}, {%10,%11,%12,%13};\n"
        : "=f"(d[0]), "=f"(d[1]), "=f"(d[2]), "=f"(d[3])
        : "r"(a[0]), "r"(a[1]), "r"(a[2]), "r"(a[3]), "r"(b0), "r"(b1),
          "f"(0.f), "f"(0.f), "f"(0.f), "f"(0.f));
}
__device__ __forceinline__ void cp16(uint32_t dst, const void* src) {
    asm volatile("cp.async.cg.shared.global [%0], [%1], 16;" :: "r"(dst), "l"(src));
}
#define CP_COMMIT() asm volatile("cp.async.commit_group;" ::: "memory")
#define CP_WAIT0()  asm volatile("cp.async.wait_group 0;" ::: "memory")

__device__ __forceinline__ void ln_relu12(const float* x, const float* g, const float* b, float* y) {
    float mu = 0.f;
    #pragma unroll
    for (int j = 0; j < 12; j++) mu += x[j];
    mu *= (1.f / 12.f);
    float var = 0.f;
    #pragma unroll
    for (int j = 0; j < 12; j++) { float d = x[j] - mu; var += d * d; }
    var *= (1.f / 12.f);
    float inv = rsqrtf(var + 1e-5f);
    #pragma unroll
    for (int j = 0; j < 12; j++) {
        float t = (x[j] - mu) * inv * g[j] + b[j];
        y[j] = t > 0.f ? t : 0.f;
    }
}

// ---------------------------------------------------------------------------
// Kernel 0: prep — block 0: bias MLP; blocks 1..1536: (bh, 128-kv chunk)
// ---------------------------------------------------------------------------
__global__ __launch_bounds__(256) void prep_kernel(
    const float* __restrict__ k, const float* __restrict__ v,
    const float* __restrict__ pw,  const float* __restrict__ pb,
    const float* __restrict__ g1,  const float* __restrict__ b1,
    const float* __restrict__ w1,  const float* __restrict__ bb1,
    const float* __restrict__ g2,  const float* __restrict__ b2,
    const float* __restrict__ w2,  const float* __restrict__ bb2,
    const float* __restrict__ g3,  const float* __restrict__ b3,
    const float* __restrict__ w3,  const float* __restrict__ bb3)
{
    extern __shared__ float sh[];
    const int t = threadIdx.x;

    if (blockIdx.x == 0) {
        if (t < 36)  sh[t] = pw[t];
        if (t < 12) {
            sh[36+t]=pb[t];  sh[48+t]=g1[t]; sh[60+t]=b1[t]; sh[216+t]=bb1[t];
            sh[228+t]=g2[t]; sh[240+t]=b2[t]; sh[396+t]=bb2[t];
            sh[408+t]=g3[t]; sh[420+t]=b3[t];
        }
        if (t < 144) { sh[72+t]=w1[t]; sh[252+t]=w2[t]; }
        if (t < 72)  sh[432+t] = w3[t];
        if (t < 6)   sh[504+t] = bb3[t];
        __syncthreads();
        if (t < NIDX) {
            float c0 = -7.0f, c1 = (float)(t / 15) - 7.0f, c2 = (float)(t % 15) - 7.0f;
            float x[12], y[12];
            #pragma unroll
            for (int j = 0; j < 12; j++)
                x[j] = c0 * sh[j] + c1 * sh[12 + j] + c2 * sh[24 + j] + sh[36 + j];
            ln_relu12(x, sh+48, sh+60, y);
            #pragma unroll
            for (int j = 0; j < 12; j++) {
                float s = sh[216 + j];
                #pragma unroll
                for (int i = 0; i < 12; i++) s += y[i] * sh[72 + i * 12 + j];
                x[j] = s;
            }
            ln_relu12(x, sh+228, sh+240, y);
            #pragma unroll
            for (int j = 0; j < 12; j++) {
                float s = sh[396 + j];
                #pragma unroll
                for (int i = 0; i < 12; i++) s += y[i] * sh[252 + i * 12 + j];
                x[j] = s;
            }
            ln_relu12(x, sh+408, sh+420, y);
            #pragma unroll
            for (int h = 0; h < H_; h++) {
                float s = sh[504 + h];
                #pragma unroll
                for (int i = 0; i < 12; i++) s += y[i] * sh[432 + i * H_ + h];
                g_pos[h * NIDX + t] = s;
            }
        }
        return;
    }

    const int bi = blockIdx.x - 1;
    const int bh = bi >> 2, c = bi & 3;      // kv rows 128c..128c+127
    const float* kb = k + (size_t)bh * N_ * D_ + (size_t)(128 * c) * D_;
    const float* vb = v + (size_t)bh * N_ * D_ + (size_t)(128 * c) * D_;

    // K image (128 rows of this chunk)
    for (int i = t; i < 128 * 4; i += 256) {
        int n = i >> 2, le = i & 3, c0 = le * 2;
        const float* row = kb + (size_t)n * D_;
        float2 f0 = *(const float2*)(row + c0);
        float2 f1 = *(const float2*)(row + c0 + 8);
        float2 f2 = *(const float2*)(row + c0 + 16);
        float2 f3 = *(const float2*)(row + c0 + 24);
        uint4 w;
        w.x = pkf16(f0.x, f0.y); w.y = pkf16(f1.x, f1.y);
        w.z = pkf16(f2.x, f2.y); w.w = pkf16(f3.x, f3.y);
        g_K[(size_t)bh * (N_ * 4) + (size_t)(128 * c) * 4 + i] = w;
    }

    // V: stage 128x32 fp32, transpose-pack 16 u4 per d-row
    for (int i = t; i < 128 * D_; i += 256) {
        int kv = i >> 5, d = i & 31;
        sh[kv * 33 + d] = vb[i];
    }
    __syncthreads();
    for (int i = t; i < D_ * 16; i += 256) {
        int d = i >> 4, wl = i & 15;
        int kpl = wl >> 2, le = wl & 3;
        int k0 = 32 * kpl + 2 * le;
        uint4 w;
        w.x = pkf16(sh[(k0 +  0) * 33 + d], sh[(k0 +  1) * 33 + d]);
        w.y = pkf16(sh[(k0 +  8) * 33 + d], sh[(k0 +  9) * 33 + d]);
        w.z = pkf16(sh[(k0 + 16) * 33 + d], sh[(k0 + 17) * 33 + d]);
        w.w = pkf16(sh[(k0 + 24) * 33 + d], sh[(k0 + 25) * 33 + d]);
        g_V[(size_t)bh * (D_ * 64) + d * 64 + 16 * c + wl] = w;
    }
}

// ---------------------------------------------------------------------------
// Kernel 1: flash attention — f16x2 softmax path, l via ones-MMA
// ---------------------------------------------------------------------------
__global__ __launch_bounds__(256, 2) void attn_kernel(
    const float* __restrict__ q, float* __restrict__ out)
{
    extern __shared__ unsigned char smem[];
    uint32_t sb;
    asm("{ .reg .u64 t; cvta.to.shared.u64 t, %1; cvt.u32.u64 %0, t; }" : "=r"(sb) : "l"(smem));
    float* biasSm = (float*)(smem + SB_OFF);

    const int qt = blockIdx.x, head = blockIdx.y, batch = blockIdx.z;
    const int bh = batch * H_ + head;
    const size_t bhOff = (size_t)bh * N_ * D_;
    const float* qb = q + bhOff;
    const int tid = threadIdx.x;

    if (tid < NIDX) biasSm[tid] = g_pos[head * NIDX + tid] * LOG2E;

    // one-shot KV fill
    {
        const uint4* gk = g_K + (size_t)bh * (N_ * 4);
        const uint4* gv = g_V + (size_t)bh * (D_ * 64);
        for (int i = tid; i < N_ * 4; i += 256)
            cp16(sb + SK_OFF + i * 16, gk + i);
        for (int i = tid; i < D_ * 64; i += 256) {
            int d = i >> 6, w_ = i & 63;
            cp16(sb + SV_OFF + (d * VROW_U + w_) * 16, gv + i);
        }
        CP_COMMIT();
    }

    const int warp = tid >> 5, lane = tid & 31;
    const int lq = lane >> 2, le = lane & 3, e0 = le * 2;
    const int r0 = qt * 128 + warp * 16 + lq;
    const int r1 = r0 + 8;
    const int sq0 = (r0 >> 6) + ((r0 >> 3) & 7) + (r0 & 7);

    // Q fragments (single fp16, scale folded into log2 domain)
    const float scale = 0.17677669529663687f * LOG2E;
    uint32_t aq[2][4];
    #pragma unroll
    for (int ks = 0; ks < 2; ks++) {
        int cb = ks * 16 + e0;
        aq[ks][0] = pkf16(qb[(size_t)r0 * D_ + cb] * scale,     qb[(size_t)r0 * D_ + cb + 1] * scale);
        aq[ks][1] = pkf16(qb[(size_t)r1 * D_ + cb] * scale,     qb[(size_t)r1 * D_ + cb + 1] * scale);
        aq[ks][2] = pkf16(qb[(size_t)r0 * D_ + cb + 8] * scale, qb[(size_t)r0 * D_ + cb + 9] * scale);
        aq[ks][3] = pkf16(qb[(size_t)r1 * D_ + cb + 8] * scale, qb[(size_t)r1 * D_ + cb + 9] * scale);
    }

    CP_WAIT0();
    __syncthreads();

    // bias pairs in f16x2 registers: bh2[u] = (br[u], br[u+1]), br[u] = biasSm[A1-u]
    const int A1 = sq0 + 22 - e0;          // in [16,42]
    uint32_t bh2[16];
    {
        float br[17];
        #pragma unroll
        for (int u = 0; u < 17; u++) br[u] = biasSm[A1 - u];
        #pragma unroll
        for (int u = 0; u < 16; u++) bh2[u] = pkf16(br[u], br[u + 1]);
    }

    const uint4* Ks = (const uint4*)(smem + SK_OFF);
    const uint4* Vs = (const uint4*)(smem + SV_OFF);
    const uint32_t ONES = 0x3C003C00u;

    float O[4][4];
    #pragma unroll
    for (int d = 0; d < 4; d++)
        #pragma unroll
        for (int j = 0; j < 4; j++) O[d][j] = 0.f;
    float L[4] = {0.f, 0.f, 0.f, 0.f};

    #pragma unroll
    for (int ch64 = 0; ch64 < 8; ch64++) {
        // S = Q K^T (fresh accumulators, C=0)
        float S[8][4];
        #pragma unroll
        for (int nt = 0; nt < 8; nt++) {
            uint4 w = Ks[(ch64 * 64 + nt * 8 + lq) * 4 + le];
            mma_f16_zc(S[nt], aq[0], w.x, w.y);
            mma_f16(S[nt], aq[1], w.z, w.w);
        }
        // pack -> +bias (HADD2) -> ex2.f16x2
        uint32_t P01[8], P23[8];
        #pragma unroll
        for (int nt = 0; nt < 8; nt++) {
            uint32_t a01 = pkf16(S[nt][0], S[nt][1]);   // (r0,e0),(r0,e0+1)
            uint32_t a23 = pkf16(S[nt][2], S[nt][3]);   // (r1,e0),(r1,e0+1)
            a01 = hadd2(a01, bh2[ch64 + nt + 1]);
            a23 = hadd2(a23, bh2[ch64 + nt]);
            P01[nt] = hex2(a01);
            P23[nt] = hex2(a23);
        }
        // O += P V ; L += P * ones
        #pragma unroll
        for (int kp2 = 0; kp2 < 2; kp2++) {
            const int j0 = kp2 * 2, j1 = j0 + 1;
            uint32_t ap0[4] = {P01[2*j0], P23[2*j0], P01[2*j0+1], P23[2*j0+1]};
            uint32_t ap1[4] = {P01[2*j1], P23[2*j1], P01[2*j1+1], P23[2*j1+1]};
            const int wb = (ch64 * 2 + kp2) * 4 + le;
            #pragma unroll
            for (int dt = 0; dt < 4; dt++) {
                uint4 w = Vs[(dt * 8 + lq) * VROW_U + wb];
                mma_f16(O[dt], ap0, w.x, w.y);
                mma_f16(O[dt], ap1, w.z, w.w);
            }
            mma_f16(L, ap0, ONES, ONES);
            mma_f16(L, ap1, ONES, ONES);
        }
    }

    // finalize: L[0] = l(r0), L[2] = l(r1) (all lanes hold full row sums)
    float i0 = 1.f / L[0], i1 = 1.f / L[2];
    float* ob = out + bhOff;
    #pragma unroll
    for (int dt = 0; dt < 4; dt++) {
        int c = dt * 8 + e0;
        float2 o01; o01.x = O[dt][0] * i0; o01.y = O[dt][1] * i0;
        float2 o23; o23.x = O[dt][2] * i1; o23.y = O[dt][3] * i1;
        *(float2*)(ob + (size_t)r0 * D_ + c) = o01;
        *(float2*)(ob + (size_t)r1 * D_ + c) = o23;
    }
}

// ---------------------------------------------------------------------------
extern "C" void kernel_launch(void* const* d_in, const int* in_sizes, int n_in,
                              void* d_out, int out_size)
{
    const float* q = (const float*)d_in[0];
    const float* k = (const float*)d_in[1];
    const float* v = (const float*)d_in[2];
    int base = (in_sizes[3] == 36) ? 3 : 6;
    const float* pw  = (const float*)d_in[base + 0];
    const float* pb  = (const float*)d_in[base + 1];
    const float* g1  = (const float*)d_in[base + 2];
    const float* b1  = (const float*)d_in[base + 3];
    const float* w1  = (const float*)d_in[base + 4];
    const float* bb1 = (const float*)d_in[base + 5];
    const float* g2  = (const float*)d_in[base + 6];
    const float* b2  = (const float*)d_in[base + 7];
    const float* w2  = (const float*)d_in[base + 8];
    const float* bb2 = (const float*)d_in[base + 9];
    const float* g3  = (const float*)d_in[base + 10];
    const float* b3  = (const float*)d_in[base + 11];
    const float* w3  = (const float*)d_in[base + 12];
    const float* bb3 = (const float*)d_in[base + 13];
    float* out = (float*)d_out;

    cudaFuncSetAttribute(prep_kernel, cudaFuncAttributeMaxDynamicSharedMemorySize, PREP_SMEM);
    cudaFuncSetAttribute(attn_kernel, cudaFuncAttributeMaxDynamicSharedMemorySize, SMEM_SZ);

    prep_kernel<<<BH_ * 4 + 1, 256, PREP_SMEM>>>(k, v, pw, pb, g1, b1, w1, bb1,
                                                 g2, b2, w2, bb2, g3, b3, w3, bb3);

    dim3 grid(N_ / 128, H_, B_);
    attn_kernel<<<grid, 256, SMEM_SZ>>>(q, out);
}

// round 12
// speedup vs baseline: 1.4986x; 1.1386x over previous
#include <cuda_runtime.h>
#include <cuda_fp16.h>
#include <stdint.h>

#define B_    64
#define H_    6
#define N_    512
#define D_    32
#define NIDX  43
#define LOG2E 1.4426950408889634f

// smem: K image 32KB | V image 32 x 68 u4 | V scratch 128x36 f32 | wts | bias
#define SK_OFF   0
#define SV_OFF   32768
#define VROW_U   68
#define VST_OFF  (SV_OFF + D_*VROW_U*16)    // 67584
#define WT_OFF   (VST_OFF + 128*36*4)       // 86016
#define SB_OFF   (WT_OFF + 2048)            // 88064
#define SMEM_SZ  (SB_OFF + 192)             // 88256 -> 2 CTAs/SM

// ---------------- helpers ----------------
__device__ __forceinline__ uint32_t pkf16(float x0, float x1) {
    uint32_t r; asm("cvt.rn.f16x2.f32 %0, %1, %2;" : "=r"(r) : "f"(x1), "f"(x0)); return r;
}
__device__ __forceinline__ uint32_t hadd2(uint32_t a, uint32_t b) {
    uint32_t r; asm("add.rn.f16x2 %0, %1, %2;" : "=r"(r) : "r"(a), "r"(b)); return r;
}
__device__ __forceinline__ uint32_t hex2(uint32_t a) {
    uint32_t r; asm("ex2.approx.f16x2 %0, %1;" : "=r"(r) : "r"(a)); return r;
}
__device__ __forceinline__ void mma_f16(float c[4], const uint32_t a[4], uint32_t b0, uint32_t b1) {
    asm volatile(
        "mma.sync.aligned.m16n8k16.row.col.f32.f16.f16.f32 "
        "{%0,%1,%2,%3}, {%4,%5,%6,%7}, {%8,%9}, {%0,%1,%2,%3};\n"
        : "+f"(c[0]), "+f"(c[1]), "+f"(c[2]), "+f"(c[3])
        : "r"(a[0]), "r"(a[1]), "r"(a[2]), "r"(a[3]), "r"(b0), "r"(b1));
}
__device__ __forceinline__ void mma_f16_zc(float d[4], const uint32_t a[4], uint32_t b0, uint32_t b1) {
    asm volatile(
        "mma.sync.aligned.m16n8k16.row.col.f32.f16.f16.f32 "
        "{%0,%1,%2,%3}, {%4,%5,%6,%7}, {%8,%9}, {%10,%11,%12,%13};\n"
        : "=f"(d[0]), "=f"(d[1]), "=f"(d[2]), "=f"(d[3])
        : "r"(a[0]), "r"(a[1]), "r"(a[2]), "r"(a[3]), "r"(b0), "r"(b1),
          "f"(0.f), "f"(0.f), "f"(0.f), "f"(0.f));
}
__device__ __forceinline__ void cp16(uint32_t dst, const void* src) {
    asm volatile("cp.async.cg.shared.global [%0], [%1], 16;" :: "r"(dst), "l"(src));
}
#define CP_COMMIT() asm volatile("cp.async.commit_group;" ::: "memory")
#define CP_WAIT0()  asm volatile("cp.async.wait_group 0;" ::: "memory")

__device__ __forceinline__ void ln_relu12(const float* x, const float* g, const float* b, float* y) {
    float mu = 0.f;
    #pragma unroll
    for (int j = 0; j < 12; j++) mu += x[j];
    mu *= (1.f / 12.f);
    float var = 0.f;
    #pragma unroll
    for (int j = 0; j < 12; j++) { float d = x[j] - mu; var += d * d; }
    var *= (1.f / 12.f);
    float inv = rsqrtf(var + 1e-5f);
    #pragma unroll
    for (int j = 0; j < 12; j++) {
        float t = (x[j] - mu) * inv * g[j] + b[j];
        y[j] = t > 0.f ? t : 0.f;
    }
}

// ---------------------------------------------------------------------------
// Single fused kernel: K/V convert + MLP prologue, then two 128-q-row tiles
// ---------------------------------------------------------------------------
__global__ __launch_bounds__(256, 2) void attn_kernel(
    const float* __restrict__ q, const float* __restrict__ k,
    const float* __restrict__ v, float* __restrict__ out,
    const float* __restrict__ pw,  const float* __restrict__ pb,
    const float* __restrict__ g1,  const float* __restrict__ b1,
    const float* __restrict__ w1,  const float* __restrict__ bb1,
    const float* __restrict__ g2,  const float* __restrict__ b2,
    const float* __restrict__ w2,  const float* __restrict__ bb2,
    const float* __restrict__ g3,  const float* __restrict__ b3,
    const float* __restrict__ w3,  const float* __restrict__ bb3)
{
    extern __shared__ unsigned char smem[];
    uint32_t sb;
    asm("{ .reg .u64 t; cvta.to.shared.u64 t, %1; cvt.u32.u64 %0, t; }" : "=r"(sb) : "l"(smem));
    float* vs     = (float*)(smem + VST_OFF);
    float* wts    = (float*)(smem + WT_OFF);
    float* biasSm = (float*)(smem + SB_OFF);

    const int qt2 = blockIdx.x, head = blockIdx.y, batch = blockIdx.z;
    const int bh = batch * H_ + head;
    const size_t bhOff = (size_t)bh * N_ * D_;
    const float* qb = q + bhOff;
    const float* kb = k + bhOff;
    const float* vb = v + bhOff;
    const int tid = threadIdx.x;

    // ---- phase A: weight LDGs + V chunk-0 stage (cp.async) + K convert ----
    if (tid < 36)  wts[tid] = pw[tid];
    if (tid < 12) {
        wts[36+tid]=pb[tid];  wts[48+tid]=g1[tid]; wts[60+tid]=b1[tid]; wts[216+tid]=bb1[tid];
        wts[228+tid]=g2[tid]; wts[240+tid]=b2[tid]; wts[396+tid]=bb2[tid];
        wts[408+tid]=g3[tid]; wts[420+tid]=b3[tid];
    }
    if (tid < 144) { wts[72+tid]=w1[tid]; wts[252+tid]=w2[tid]; }
    if (tid >= 144 && tid < 216) wts[432+tid-144] = w3[tid-144];
    if (tid >= 216 && tid < 222) wts[504+tid-216] = bb3[tid-216];

    // V chunk 0: kv rows 0..127 -> scratch (16B cp.async)
    for (int i = tid; i < 128 * 8; i += 256) {
        int kv = i >> 3, dch = i & 7;
        cp16(sb + VST_OFF + (kv * 36 + dch * 4) * 4, vb + kv * 32 + dch * 4);
    }
    CP_COMMIT();

    // K convert: raw fp32 -> fp16 image (coalesced LDG, cvt, STS)
    {
        uint4* Kimg = (uint4*)(smem + SK_OFF);
        for (int i = tid; i < N_ * 4; i += 256) {
            int n = i >> 2, le = i & 3, c0 = le * 2;
            const float* row = kb + (size_t)n * D_;
            float2 f0 = *(const float2*)(row + c0);
            float2 f1 = *(const float2*)(row + c0 + 8);
            float2 f2 = *(const float2*)(row + c0 + 16);
            float2 f3 = *(const float2*)(row + c0 + 24);
            uint4 w;
            w.x = pkf16(f0.x, f0.y); w.y = pkf16(f1.x, f1.y);
            w.z = pkf16(f2.x, f2.y); w.w = pkf16(f3.x, f3.y);
            Kimg[i] = w;
        }
    }
    __syncthreads();   // wts visible

    // MLP: this head's 43 bias values (tids 0..42; once per CTA)
    if (tid < NIDX) {
        float c0 = -7.0f, c1 = (float)(tid / 15) - 7.0f, c2 = (float)(tid % 15) - 7.0f;
        float x[12], y[12];
        #pragma unroll
        for (int j = 0; j < 12; j++)
            x[j] = c0 * wts[j] + c1 * wts[12 + j] + c2 * wts[24 + j] + wts[36 + j];
        ln_relu12(x, wts+48, wts+60, y);
        #pragma unroll
        for (int j = 0; j < 12; j++) {
            float s = wts[216 + j];
            #pragma unroll
            for (int i = 0; i < 12; i++) s += y[i] * wts[72 + i * 12 + j];
            x[j] = s;
        }
        ln_relu12(x, wts+228, wts+240, y);
        #pragma unroll
        for (int j = 0; j < 12; j++) {
            float s = wts[396 + j];
            #pragma unroll
            for (int i = 0; i < 12; i++) s += y[i] * wts[252 + i * 12 + j];
            x[j] = s;
        }
        ln_relu12(x, wts+408, wts+420, y);
        float s = wts[504 + head];
        #pragma unroll
        for (int i = 0; i < 12; i++) s += y[i] * wts[432 + i * H_ + head];
        biasSm[tid] = s * LOG2E;
    }

    // ---- V: 4 chunks of 128 kv, stage (cp.async) -> transpose-pack (STS) ----
    for (int c = 0; c < 4; c++) {
        CP_WAIT0();
        __syncthreads();           // scratch chunk c ready everywhere
        uint4* Vimg = (uint4*)(smem + SV_OFF);
        for (int i = tid; i < D_ * 16; i += 256) {
            int d = i >> 4, wl = i & 15;            // wl = kpl*4 + le
            int kpl = wl >> 2, le = wl & 3;
            int k0 = 32 * kpl + 2 * le;
            uint4 w;
            w.x = pkf16(vs[(k0 +  0) * 36 + d], vs[(k0 +  1) * 36 + d]);
            w.y = pkf16(vs[(k0 +  8) * 36 + d], vs[(k0 +  9) * 36 + d]);
            w.z = pkf16(vs[(k0 + 16) * 36 + d], vs[(k0 + 17) * 36 + d]);
            w.w = pkf16(vs[(k0 + 24) * 36 + d], vs[(k0 + 25) * 36 + d]);
            Vimg[d * VROW_U + 16 * c + wl] = w;     // global w = 16c + wl
        }
        __syncthreads();           // scratch free for next stage
        if (c < 3) {
            const float* vcb = vb + (size_t)(128 * (c + 1)) * D_;
            for (int i = tid; i < 128 * 8; i += 256) {
                int kv = i >> 3, dch = i & 7;
                cp16(sb + VST_OFF + (kv * 36 + dch * 4) * 4, vcb + kv * 32 + dch * 4);
            }
            CP_COMMIT();
        }
    }
    // K image, V image, biasSm all visible (last __syncthreads above)

    const int warp = tid >> 5, lane = tid & 31;
    const int lq = lane >> 2, le = lane & 3, e0 = le * 2;
    const uint4* Ks = (const uint4*)(smem + SK_OFF);
    const uint4* Vs = (const uint4*)(smem + SV_OFF);
    const uint32_t ONES = 0x3C003C00u;
    const float scale = 0.17677669529663687f * LOG2E;
    float* ob = out + bhOff;

    // ---- two 128-row q tiles against the resident K/V ----
    for (int mt = 0; mt < 2; mt++) {
        const int r0 = qt2 * 256 + mt * 128 + warp * 16 + lq;
        const int r1 = r0 + 8;
        const int sq0 = (r0 >> 6) + ((r0 >> 3) & 7) + (r0 & 7);

        // Q fragments (single fp16, log2-domain scale)
        uint32_t aq[2][4];
        #pragma unroll
        for (int ks = 0; ks < 2; ks++) {
            int cb = ks * 16 + e0;
            aq[ks][0] = pkf16(qb[(size_t)r0 * D_ + cb] * scale,     qb[(size_t)r0 * D_ + cb + 1] * scale);
            aq[ks][1] = pkf16(qb[(size_t)r1 * D_ + cb] * scale,     qb[(size_t)r1 * D_ + cb + 1] * scale);
            aq[ks][2] = pkf16(qb[(size_t)r0 * D_ + cb + 8] * scale, qb[(size_t)r0 * D_ + cb + 9] * scale);
            aq[ks][3] = pkf16(qb[(size_t)r1 * D_ + cb + 8] * scale, qb[(size_t)r1 * D_ + cb + 9] * scale);
        }

        // bias pairs (f16x2)
        const int A1 = sq0 + 22 - e0;
        uint32_t bh2[16];
        {
            float br[17];
            #pragma unroll
            for (int u = 0; u < 17; u++) br[u] = biasSm[A1 - u];
            #pragma unroll
            for (int u = 0; u < 16; u++) bh2[u] = pkf16(br[u], br[u + 1]);
        }

        float O[4][4];
        #pragma unroll
        for (int d = 0; d < 4; d++)
            #pragma unroll
            for (int j = 0; j < 4; j++) O[d][j] = 0.f;
        float L[4] = {0.f, 0.f, 0.f, 0.f};

        #pragma unroll
        for (int ch64 = 0; ch64 < 8; ch64++) {
            float S[8][4];
            #pragma unroll
            for (int nt = 0; nt < 8; nt++) {
                uint4 w = Ks[(ch64 * 64 + nt * 8 + lq) * 4 + le];
                mma_f16_zc(S[nt], aq[0], w.x, w.y);
                mma_f16(S[nt], aq[1], w.z, w.w);
            }
            uint32_t P01[8], P23[8];
            #pragma unroll
            for (int nt = 0; nt < 8; nt++) {
                uint32_t a01 = pkf16(S[nt][0], S[nt][1]);
                uint32_t a23 = pkf16(S[nt][2], S[nt][3]);
                a01 = hadd2(a01, bh2[ch64 + nt + 1]);
                a23 = hadd2(a23, bh2[ch64 + nt]);
                P01[nt] = hex2(a01);
                P23[nt] = hex2(a23);
            }
            #pragma unroll
            for (int kp2 = 0; kp2 < 2; kp2++) {
                const int j0 = kp2 * 2, j1 = j0 + 1;
                uint32_t ap0[4] = {P01[2*j0], P23[2*j0], P01[2*j0+1], P23[2*j0+1]};
                uint32_t ap1[4] = {P01[2*j1], P23[2*j1], P01[2*j1+1], P23[2*j1+1]};
                const int wb = (ch64 * 2 + kp2) * 4 + le;
                #pragma unroll
                for (int dt = 0; dt < 4; dt++) {
                    uint4 w = Vs[(dt * 8 + lq) * VROW_U + wb];
                    mma_f16(O[dt], ap0, w.x, w.y);
                    mma_f16(O[dt], ap1, w.z, w.w);
                }
                mma_f16(L, ap0, ONES, ONES);
                mma_f16(L, ap1, ONES, ONES);
            }
        }

        // finalize tile
        float i0 = 1.f / L[0], i1 = 1.f / L[2];
        #pragma unroll
        for (int dt = 0; dt < 4; dt++) {
            int c = dt * 8 + e0;
            float2 o01; o01.x = O[dt][0] * i0; o01.y = O[dt][1] * i0;
            float2 o23; o23.x = O[dt][2] * i1; o23.y = O[dt][3] * i1;
            *(float2*)(ob + (size_t)r0 * D_ + c) = o01;
            *(float2*)(ob + (size_t)r1 * D_ + c) = o23;
        }
    }
}

// ---------------------------------------------------------------------------
extern "C" void kernel_launch(void* const* d_in, const int* in_sizes, int n_in,
                              void* d_out, int out_size)
{
    const float* q = (const float*)d_in[0];
    const float* k = (const float*)d_in[1];
    const float* v = (const float*)d_in[2];
    int base = (in_sizes[3] == 36) ? 3 : 6;
    const float* pw  = (const float*)d_in[base + 0];
    const float* pb  = (const float*)d_in[base + 1];
    const float* g1  = (const float*)d_in[base + 2];
    const float* b1  = (const float*)d_in[base + 3];
    const float* w1  = (const float*)d_in[base + 4];
    const float* bb1 = (const float*)d_in[base + 5];
    const float* g2  = (const float*)d_in[base + 6];
    const float* b2  = (const float*)d_in[base + 7];
    const float* w2  = (const float*)d_in[base + 8];
    const float* bb2 = (const float*)d_in[base + 9];
    const float* g3  = (const float*)d_in[base + 10];
    const float* b3  = (const float*)d_in[base + 11];
    const float* w3  = (const float*)d_in[base + 12];
    const float* bb3 = (const float*)d_in[base + 13];
    float* out = (float*)d_out;

    cudaFuncSetAttribute(attn_kernel, cudaFuncAttributeMaxDynamicSharedMemorySize, SMEM_SZ);

    dim3 grid(2, H_, B_);
    attn_kernel<<<grid, 256, SMEM_SZ>>>(q, k, v, out, pw, pb, g1, b1, w1, bb1,
                                        g2, b2, w2, bb2, g3, b3, w3, bb3);
}